// round 4
// baseline (speedup 1.0000x reference)
#include <cuda_runtime.h>
#include <cuda_bf16.h>

// y[i] = dot(x[i, 0:32], w[0:32]) + w[32]
// Persistent grid-stride: 1024 blocks x 256 threads = 8192 warps; each warp
// handles exactly N/32/8192 = 16 row-blocks of 32 rows. Single wave, no tail.
// Per row-block: 8 front-batched coalesced LDG.128 (streaming), FMA + 3x
// shfl_xor butterfly per group of 8 lanes, register transpose via one shfl,
// one coalesced 128B STG per warp.
__global__ void __launch_bounds__(256, 8)
linreg_kernel(const float4* __restrict__ x4,
              const float*  __restrict__ w,
              float*        __restrict__ y,
              int nrb)   // number of 32-row blocks (n/32, n divisible by 32)
{
    const int lane = threadIdx.x & 31;
    const int lig  = lane & 7;

    const int warpsPerGrid = (gridDim.x * blockDim.x) >> 5;
    int wb = blockIdx.x * (blockDim.x >> 5) + (threadIdx.x >> 5);

    const float4 wv  = __ldg(reinterpret_cast<const float4*>(w) + lig);
    const float bias = __ldg(w + 32);

    const int src = ((lane & 3) << 3) | (lane >> 2);  // transpose source lane

    for (; wb < nrb; wb += warpsPerGrid) {
        const float4* base = x4 + (size_t)wb * 256 + lane;  // 32 rows * 8 f4

        // ---- all 8 loads in flight before any consumer ----
        float4 v0 = __ldcs(base + 0 * 32);
        float4 v1 = __ldcs(base + 1 * 32);
        float4 v2 = __ldcs(base + 2 * 32);
        float4 v3 = __ldcs(base + 3 * 32);
        float4 v4 = __ldcs(base + 4 * 32);
        float4 v5 = __ldcs(base + 5 * 32);
        float4 v6 = __ldcs(base + 6 * 32);
        float4 v7 = __ldcs(base + 7 * 32);

#define DOT_RED(S, V)                                                          \
        float S = fmaf((V).x, wv.x,                                            \
                  fmaf((V).y, wv.y, fmaf((V).z, wv.z, (V).w * wv.w)));         \
        S += __shfl_xor_sync(0xffffffffu, S, 4);                               \
        S += __shfl_xor_sync(0xffffffffu, S, 2);                               \
        S += __shfl_xor_sync(0xffffffffu, S, 1);

        DOT_RED(s0, v0) DOT_RED(s1, v1) DOT_RED(s2, v2) DOT_RED(s3, v3)
        DOT_RED(s4, v4) DOT_RED(s5, v5) DOT_RED(s6, v6) DOT_RED(s7, v7)
#undef DOT_RED

        // lane t wants row (wb*32 + t) = iteration (t>>2), group (t&3).
        // Source lane u = (t&3)*8 + (t>>2); u exports its s[lig].
        float val = s0;
        val = (lig == 1) ? s1 : val;
        val = (lig == 2) ? s2 : val;
        val = (lig == 3) ? s3 : val;
        val = (lig == 4) ? s4 : val;
        val = (lig == 5) ? s5 : val;
        val = (lig == 6) ? s6 : val;
        val = (lig == 7) ? s7 : val;

        float out = __shfl_sync(0xffffffffu, val, src) + bias;
        __stcs(y + wb * 32 + lane, out);   // 128B coalesced
    }
}

extern "C" void kernel_launch(void* const* d_in, const int* in_sizes, int n_in,
                              void* d_out, int out_size)
{
    const float* x = (const float*)d_in[0];   // [N, 32] fp32
    const float* w = (const float*)d_in[1];   // [33, 1] fp32
    float* y = (float*)d_out;                 // [N] fp32

    const int n   = in_sizes[0] / 32;         // rows (4194304, divisible by 32)
    const int nrb = n / 32;                   // 131072 row-blocks
    // 1024 blocks x 8 warps = 8192 warps -> exactly 16 row-blocks per warp;
    // single resident wave on 148+ SMs, perfectly balanced.
    linreg_kernel<<<1024, 256>>>(
        reinterpret_cast<const float4*>(x), w, y, nrb);
}

// round 5
// speedup vs baseline: 1.2807x; 1.2807x over previous
#include <cuda_runtime.h>
#include <cuda_bf16.h>

// y[i] = dot(x[i, 0:32], w[0:32]) + w[32]
// One-shot warps (no persistent loop): each warp handles 64 rows (2 blocks of
// 32). All 16 coalesced LDG.128 (8 KB) issued before any consumer, then the
// two blocks are reduced and stored as two coalesced 128B STGs.
__global__ void __launch_bounds__(256, 3)
linreg_kernel(const float4* __restrict__ x4,
              const float*  __restrict__ w,
              float*        __restrict__ y,
              int n)
{
    const int lane = threadIdx.x & 31;
    const int lig  = lane & 7;

    const int warp = blockIdx.x * (blockDim.x >> 5) + (threadIdx.x >> 5);
    const int row0 = warp << 6;                 // 64 rows per warp
    if (row0 >= n) return;

    const float4 wv  = __ldg(reinterpret_cast<const float4*>(w) + lig);
    const float bias = __ldg(w + 32);

    const float4* base = x4 + (size_t)row0 * 8 + lane;

    // ---- all 16 loads in flight before any consumer ----
    float4 a0 = __ldcs(base +  0 * 32);
    float4 a1 = __ldcs(base +  1 * 32);
    float4 a2 = __ldcs(base +  2 * 32);
    float4 a3 = __ldcs(base +  3 * 32);
    float4 a4 = __ldcs(base +  4 * 32);
    float4 a5 = __ldcs(base +  5 * 32);
    float4 a6 = __ldcs(base +  6 * 32);
    float4 a7 = __ldcs(base +  7 * 32);
    float4 b0 = __ldcs(base +  8 * 32);
    float4 b1 = __ldcs(base +  9 * 32);
    float4 b2 = __ldcs(base + 10 * 32);
    float4 b3 = __ldcs(base + 11 * 32);
    float4 b4 = __ldcs(base + 12 * 32);
    float4 b5 = __ldcs(base + 13 * 32);
    float4 b6 = __ldcs(base + 14 * 32);
    float4 b7 = __ldcs(base + 15 * 32);

#define DOT_RED(S, V)                                                          \
    float S = fmaf((V).x, wv.x,                                                \
              fmaf((V).y, wv.y, fmaf((V).z, wv.z, (V).w * wv.w)));             \
    S += __shfl_xor_sync(0xffffffffu, S, 4);                                   \
    S += __shfl_xor_sync(0xffffffffu, S, 2);                                   \
    S += __shfl_xor_sync(0xffffffffu, S, 1);

    const int src = ((lane & 3) << 3) | (lane >> 2);  // transpose source lane

    // ---- block A: rows row0 .. row0+31 ----
    {
        DOT_RED(s0, a0) DOT_RED(s1, a1) DOT_RED(s2, a2) DOT_RED(s3, a3)
        DOT_RED(s4, a4) DOT_RED(s5, a5) DOT_RED(s6, a6) DOT_RED(s7, a7)
        float val = s0;
        val = (lig == 1) ? s1 : val;
        val = (lig == 2) ? s2 : val;
        val = (lig == 3) ? s3 : val;
        val = (lig == 4) ? s4 : val;
        val = (lig == 5) ? s5 : val;
        val = (lig == 6) ? s6 : val;
        val = (lig == 7) ? s7 : val;
        float out = __shfl_sync(0xffffffffu, val, src) + bias;
        __stcs(y + row0 + lane, out);
    }
    // ---- block B: rows row0+32 .. row0+63 ----
    {
        DOT_RED(s0, b0) DOT_RED(s1, b1) DOT_RED(s2, b2) DOT_RED(s3, b3)
        DOT_RED(s4, b4) DOT_RED(s5, b5) DOT_RED(s6, b6) DOT_RED(s7, b7)
        float val = s0;
        val = (lig == 1) ? s1 : val;
        val = (lig == 2) ? s2 : val;
        val = (lig == 3) ? s3 : val;
        val = (lig == 4) ? s4 : val;
        val = (lig == 5) ? s5 : val;
        val = (lig == 6) ? s6 : val;
        val = (lig == 7) ? s7 : val;
        float out = __shfl_sync(0xffffffffu, val, src) + bias;
        __stcs(y + row0 + 32 + lane, out);
    }
#undef DOT_RED
}

extern "C" void kernel_launch(void* const* d_in, const int* in_sizes, int n_in,
                              void* d_out, int out_size)
{
    const float* x = (const float*)d_in[0];   // [N, 32] fp32
    const float* w = (const float*)d_in[1];   // [33, 1] fp32
    float* y = (float*)d_out;                 // [N] fp32

    const int n = in_sizes[0] / 32;           // rows
    const int threads = 256;                  // 8 warps -> 512 rows per block
    const int rows_per_block = (threads / 32) * 64;
    const int blocks = (n + rows_per_block - 1) / rows_per_block;
    linreg_kernel<<<blocks, threads>>>(
        reinterpret_cast<const float4*>(x), w, y, n);
}